// round 16
// baseline (speedup 1.0000x reference)
#include <cuda_runtime.h>
#include <cuda_fp16.h>
#include <cstdint>

#define B_   4
#define N_   4096
#define CIN  256
#define CK   128
#define COUT 256

// ---------------- scratch (no allocs allowed) ----------------
__device__ __half g_qh[B_ * N_ * CK];   // [b][n][128] fp16, pre-scaled by log2e/sqrt(128)
__device__ __half g_kh[B_ * N_ * CK];   // [b][n][128] fp16
__device__ __half g_vth[B_ * CK * N_];  // [b][d][n] fp16 (transposed V)

// ================= helpers =================
__device__ __forceinline__ uint32_t pack_h2(float lo, float hi) {
    __half2 h = __floats2half2_rn(lo, hi);
    return *(uint32_t*)&h;
}
__device__ __forceinline__ uint32_t h2exp2_(uint32_t x) {
    uint32_t r;
    asm("ex2.approx.f16x2 %0, %1;" : "=r"(r) : "r"(x));
    return r;
}
__device__ __forceinline__ void mma_f16(float* d, uint32_t a0, uint32_t a1,
                                        uint32_t a2, uint32_t a3,
                                        uint32_t b0, uint32_t b1) {
    asm volatile(
        "mma.sync.aligned.m16n8k16.row.col.f32.f16.f16.f32 "
        "{%0,%1,%2,%3}, {%4,%5,%6,%7}, {%8,%9}, {%0,%1,%2,%3};"
        : "+f"(d[0]), "+f"(d[1]), "+f"(d[2]), "+f"(d[3])
        : "r"(a0), "r"(a1), "r"(a2), "r"(a3), "r"(b0), "r"(b1));
}
__device__ __forceinline__ void ldsm_x4(uint32_t& r0, uint32_t& r1, uint32_t& r2,
                                        uint32_t& r3, uint32_t addr) {
    asm volatile("ldmatrix.sync.aligned.m8n8.x4.shared.b16 {%0,%1,%2,%3}, [%4];"
                 : "=r"(r0), "=r"(r1), "=r"(r2), "=r"(r3) : "r"(addr));
}
__device__ __forceinline__ void ldsm_x4_t(uint32_t& r0, uint32_t& r1, uint32_t& r2,
                                          uint32_t& r3, uint32_t addr) {
    asm volatile("ldmatrix.sync.aligned.m8n8.x4.trans.shared.b16 {%0,%1,%2,%3}, [%4];"
                 : "=r"(r0), "=r"(r1), "=r"(r2), "=r"(r3) : "r"(addr));
}
#define CP_ASYNC16(dst, src) \
    asm volatile("cp.async.cg.shared.global [%0], [%1], 16;" :: "r"(dst), "l"(src) : "memory")
#define CP_COMMIT() asm volatile("cp.async.commit_group;" ::: "memory")
#define CP_WAIT0()  asm volatile("cp.async.wait_group 0;" ::: "memory")

// ======== fused 3-way projection GEMM (unchanged from R15) ========
#define PJ_APADH 136
#define PJ_BPADH 72
#define PJ_BOFFH (64 * PJ_APADH)
#define PJ_SCOFF (PJ_BOFFH + 128 * PJ_BPADH)
#define PJ_SMEM  (PJ_SCOFF * 2 + 256 * 4)
#define PJ_TPAD 136

__global__ __launch_bounds__(256, 2) void gemm_tc_proj3(
    const float* __restrict__ xdec, const float* __restrict__ xenc,
    const float* __restrict__ wq, const float* __restrict__ wk,
    const float* __restrict__ wv,
    const float* __restrict__ bq, const float* __restrict__ bk,
    const float* __restrict__ bv,
    const float* __restrict__ gq, const float* __restrict__ betaq,
    const float* __restrict__ mq, const float* __restrict__ vq,
    const float* __restrict__ gk, const float* __restrict__ betak,
    const float* __restrict__ mk, const float* __restrict__ vk,
    __half* __restrict__ yqh, __half* __restrict__ ykh, __half* __restrict__ yvt) {
    extern __shared__ __half psm[];
    __half* As = psm;
    __half* Bs = psm + PJ_BOFFH;
    float* scl = (float*)(psm + PJ_SCOFF);
    float* bef = scl + 128;
    uint32_t as_u = (uint32_t)__cvta_generic_to_shared(As);
    uint32_t bs_u = (uint32_t)__cvta_generic_to_shared(Bs);

    int which = blockIdx.y;
    const float* X = (which == 0) ? xdec : xenc;
    const float* W = (which == 0) ? wq : (which == 1) ? wk : wv;

    int b = blockIdx.z;
    int n0 = blockIdx.x * 128;
    const float* Xb = X + (size_t)b * CIN * N_;

    int tid = threadIdx.x;
    int w = tid >> 5, lane = tid & 31;
    int r4 = lane >> 2, c4 = lane & 3;

    if (which != 2 && tid < 128) {
        const float* g_ = (which == 0) ? gq : gk;
        const float* v_ = (which == 0) ? vq : vk;
        const float* b_ = (which == 0) ? bq : bk;
        const float* m_ = (which == 0) ? mq : mk;
        const float* be_ = (which == 0) ? betaq : betak;
        float sv = g_[tid] * rsqrtf(v_[tid] + 1e-5f);
        float qs = (which == 0) ? 0.12752551286084110f : 1.0f;
        scl[tid] = sv * qs;
        bef[tid] = ((b_[tid] - m_[tid]) * sv + be_[tid]) * qs;
    }

    int tc = (lane & 7) + ((lane >> 4) & 1) * 8;
    int tn = ((lane >> 3) & 1) * 8;
    int brow = (lane & 7) + ((lane >> 4) & 1) * 8;
    int bk8 = ((lane >> 3) & 1) * 8;

    uint32_t a_base = as_u + (tc * PJ_APADH + w * 16 + tn) * 2;
    uint32_t b_base = bs_u + (brow * PJ_BPADH + bk8) * 2;

    float accD[16][4];
#pragma unroll
    for (int i = 0; i < 16; ++i)
#pragma unroll
        for (int j = 0; j < 4; ++j) accD[i][j] = 0.f;

    float4 ra[8];
#pragma unroll
    for (int i = 0; i < 8; ++i) {
        int idx = tid + i * 256;
        int cc = idx >> 5, nq = idx & 31;
        ra[i] = *(const float4*)(Xb + (size_t)cc * N_ + n0 + nq * 4);
    }

    for (int c0 = 0; c0 < CIN; c0 += 64) {
        __syncthreads();
#pragma unroll
        for (int i = 0; i < 8; ++i) {
            int idx = tid + i * 256;
            int cc = idx >> 5, nq = idx & 31;
            uint2 u;
            u.x = pack_h2(ra[i].x, ra[i].y);
            u.y = pack_h2(ra[i].z, ra[i].w);
            *(uint2*)(As + cc * PJ_APADH + nq * 4) = u;
        }
#pragma unroll
        for (int i = 0; i < 8; ++i) {
            int idx = tid + i * 256;
            int oo = idx >> 4, cq = idx & 15;
            float4 v = *(const float4*)(W + (size_t)oo * CIN + c0 + cq * 4);
            uint2 u;
            u.x = pack_h2(v.x, v.y);
            u.y = pack_h2(v.z, v.w);
            *(uint2*)(Bs + oo * PJ_BPADH + cq * 4) = u;
        }
        __syncthreads();

        if (c0 + 64 < CIN) {
#pragma unroll
            for (int i = 0; i < 8; ++i) {
                int idx = tid + i * 256;
                int cc = idx >> 5, nq = idx & 31;
                ra[i] = *(const float4*)(Xb + (size_t)(c0 + 64 + cc) * N_ + n0 + nq * 4);
            }
        }

#pragma unroll
        for (int kc = 0; kc < 4; ++kc) {
            uint32_t a0, a1, a2, a3;
            ldsm_x4_t(a0, a1, a2, a3, a_base + (kc * 16 * PJ_APADH) * 2);
#pragma unroll
            for (int nfp = 0; nfp < 8; ++nfp) {
                uint32_t b00, b01, b10, b11;
                ldsm_x4(b00, b01, b10, b11,
                        b_base + (nfp * 16 * PJ_BPADH + kc * 16) * 2);
                mma_f16(accD[2 * nfp], a0, a1, a2, a3, b00, b01);
                mma_f16(accD[2 * nfp + 1], a0, a1, a2, a3, b10, b11);
            }
        }
    }

    int nl = w * 16 + r4;
    int nlo = n0 + nl;
    if (which == 2) {
        __half* Yt = yvt + (size_t)b * CK * N_;
#pragma unroll
        for (int p = 0; p < 2; ++p) {
            __syncthreads();
#pragma unroll
            for (int nf = 0; nf < 8; ++nf) {
                int nfg = p * 8 + nf;
                int o = nfg * 8 + 2 * c4;
                int ol = o - p * 64;
                float b0 = __ldg(bv + o), b1 = __ldg(bv + o + 1);
                psm[ol * PJ_TPAD + nl] = __float2half(accD[nfg][0] + b0);
                psm[(ol + 1) * PJ_TPAD + nl] = __float2half(accD[nfg][1] + b1);
                psm[ol * PJ_TPAD + nl + 8] = __float2half(accD[nfg][2] + b0);
                psm[(ol + 1) * PJ_TPAD + nl + 8] = __float2half(accD[nfg][3] + b1);
            }
            __syncthreads();
            for (int idx = tid; idx < 64 * 16; idx += 256) {
                int r = idx >> 4, ck = idx & 15;
                *(uint4*)(Yt + (size_t)(p * 64 + r) * N_ + n0 + ck * 8) =
                    *(const uint4*)(psm + r * PJ_TPAD + ck * 8);
            }
        }
    } else {
        __half* Yh = ((which == 0) ? yqh : ykh) + (size_t)b * (size_t)N_ * CK;
#pragma unroll
        for (int nf = 0; nf < 16; ++nf) {
            int o = nf * 8 + 2 * c4;
            float s0 = scl[o], s1 = scl[o + 1];
            float b0 = bef[o], b1 = bef[o + 1];
            float v0 = fmaxf(accD[nf][0] * s0 + b0, 0.f);
            float v1 = fmaxf(accD[nf][1] * s1 + b1, 0.f);
            float v2 = fmaxf(accD[nf][2] * s0 + b0, 0.f);
            float v3 = fmaxf(accD[nf][3] * s1 + b1, 0.f);
            *(uint32_t*)(Yh + (size_t)nlo * CK + o) = pack_h2(v0, v1);
            *(uint32_t*)(Yh + (size_t)(nlo + 8) * CK + o) = pack_h2(v2, v3);
        }
    }
}

// ---------------- flash attention + fused output GEMM: 16 warps x 16 rows ----------------
// Warp w: qgroup=w&7 (16 query rows), khalf=w>>3 (32 of 64 keys/tile). 4 warps/SMSP.
#define QPADH  136
#define KPADH  136
#define VTPADH 72
#define KBUFH  (64 * KPADH)
#define VBUFH  (128 * VTPADH)
#define OFFK_H (128 * QPADH)
#define OFFV_H (OFFK_H + 2 * KBUFH)
#define SMEM_FLASH ((OFFV_H + 2 * VBUFH) * 2)
#define EXPSHIFT 5.770780163555854f
#define EP_LD_B 67584
#define EP_CS_B 68608

__global__ __launch_bounds__(512, 1) void flash_mma(
    const __half* __restrict__ Qh, const __half* __restrict__ Kh,
    const __half* __restrict__ Vth, const float* __restrict__ WO,
    const float* __restrict__ bo, float* __restrict__ Y) {
    extern __shared__ __half smh[];
    __half* Qs = smh;

    int tid = threadIdx.x;
    int w = tid >> 5, lane = tid & 31;
    int qgroup = w & 7, khalf = w >> 3;
    int r4 = lane >> 2, c4 = lane & 3;
    int b = blockIdx.y;
    int q0 = blockIdx.x * 128;
    const __half* Qb = Qh + ((size_t)b * N_ + q0) * CK;
    const __half* Kb = Kh + (size_t)b * N_ * CK;
    const __half* Vtb = Vth + (size_t)b * CK * N_;

    uint32_t qs_u = (uint32_t)__cvta_generic_to_shared(smh);
    uint32_t ks_u = qs_u + OFFK_H * 2;
    uint32_t vts_u = qs_u + OFFV_H * 2;

    int arow = (lane & 7) + ((lane >> 3) & 1) * 8;
    int ak8 = (lane >> 4) * 8;
    int brow = (lane & 7) + ((lane >> 4) & 1) * 8;
    int bk8 = ((lane >> 3) & 1) * 8;

    for (int idx = tid; idx < 128 * 16; idx += 512) {
        int r = idx >> 4, ck = idx & 15;
        *(uint4*)(Qs + r * QPADH + ck * 8) = *(const uint4*)(Qb + (size_t)r * CK + ck * 8);
    }
#pragma unroll
    for (int i = 0; i < 2; ++i) {
        int idx = tid + i * 512;
        int r = idx >> 4, ck = idx & 15;
        CP_ASYNC16(ks_u + (r * KPADH + ck * 8) * 2, Kb + (size_t)r * CK + ck * 8);
    }
#pragma unroll
    for (int i = 0; i < 2; ++i) {
        int idx = tid + i * 512;
        int d = idx >> 3, ck = idx & 7;
        CP_ASYNC16(vts_u + (d * VTPADH + ck * 8) * 2, Vtb + (size_t)d * N_ + ck * 8);
    }
    CP_COMMIT();
    CP_WAIT0();
    __syncthreads();

    float accO[16][4];
#pragma unroll
    for (int i = 0; i < 16; ++i)
#pragma unroll
        for (int j = 0; j < 4; ++j) accO[i][j] = 0.f;
    float accL[4];
#pragma unroll
    for (int j = 0; j < 4; ++j) accL[j] = 0.f;
    const uint32_t ONES = 0x3C003C00u;

    const int kcol = khalf * 32;
    const int NT = N_ / 64;

    uint32_t qa_base = qs_u + (((qgroup * 16 + arow) * QPADH) + ak8) * 2;
    uint32_t kb_off = ((kcol + brow) * KPADH + bk8) * 2;
    uint32_t vb_off = ((brow) * VTPADH + kcol + bk8) * 2;

    for (int t = 0; t < NT; ++t) {
        uint32_t kcur_u = ks_u + (t & 1) * (KBUFH * 2);
        uint32_t vcur_u = vts_u + (t & 1) * (VBUFH * 2);

        if (t + 1 < NT) {
            uint32_t knxt_u = ks_u + ((t + 1) & 1) * (KBUFH * 2);
            uint32_t vnxt_u = vts_u + ((t + 1) & 1) * (VBUFH * 2);
            const __half* Kg = Kb + (size_t)((t + 1) * 64) * CK;
            int k0 = (t + 1) * 64;
#pragma unroll
            for (int i = 0; i < 2; ++i) {
                int idx = tid + i * 512;
                int r = idx >> 4, ck = idx & 15;
                CP_ASYNC16(knxt_u + (r * KPADH + ck * 8) * 2, Kg + (size_t)r * CK + ck * 8);
            }
#pragma unroll
            for (int i = 0; i < 2; ++i) {
                int idx = tid + i * 512;
                int d = idx >> 3, ck = idx & 7;
                CP_ASYNC16(vnxt_u + (d * VTPADH + ck * 8) * 2,
                           Vtb + (size_t)d * N_ + k0 + ck * 8);
            }
        }
        CP_COMMIT();

        // S = Q.K^T over this warp's 16 rows x 32 keys
        float accS[4][4];
#pragma unroll
        for (int i = 0; i < 4; ++i)
#pragma unroll
            for (int j = 0; j < 4; ++j) accS[i][j] = -EXPSHIFT;
#pragma unroll
        for (int kc = 0; kc < 8; ++kc) {
            uint32_t a0, a1, a2, a3;
            ldsm_x4(a0, a1, a2, a3, qa_base + kc * 32);
            uint32_t b00, b01, b10, b11;
            ldsm_x4(b00, b01, b10, b11, kcur_u + kb_off + kc * 32);
            mma_f16(accS[0], a0, a1, a2, a3, b00, b01);
            mma_f16(accS[1], a0, a1, a2, a3, b10, b11);
            ldsm_x4(b00, b01, b10, b11, kcur_u + kb_off + (16 * KPADH) * 2 + kc * 32);
            mma_f16(accS[2], a0, a1, a2, a3, b00, b01);
            mma_f16(accS[3], a0, a1, a2, a3, b10, b11);
        }

        // P = exp2(S) packed fp16x2
        uint32_t pk[4][2];
#pragma unroll
        for (int nf = 0; nf < 4; ++nf) {
            pk[nf][0] = h2exp2_(pack_h2(accS[nf][0], accS[nf][1]));
            pk[nf][1] = h2exp2_(pack_h2(accS[nf][2], accS[nf][3]));
        }

        // O += P.V ; l via ones-mma
#pragma unroll
        for (int kc = 0; kc < 2; ++kc) {
            mma_f16(accL, pk[2 * kc][0], pk[2 * kc][1],
                    pk[2 * kc + 1][0], pk[2 * kc + 1][1], ONES, ONES);
#pragma unroll
            for (int nf = 0; nf < 16; nf += 2) {
                uint32_t b00, b01, b10, b11;
                ldsm_x4(b00, b01, b10, b11,
                        vcur_u + vb_off + (nf * 8 * VTPADH) * 2 + kc * 32);
                mma_f16(accO[nf], pk[2 * kc][0], pk[2 * kc][1],
                        pk[2 * kc + 1][0], pk[2 * kc + 1][1], b00, b01);
                mma_f16(accO[nf + 1], pk[2 * kc][0], pk[2 * kc][1],
                        pk[2 * kc + 1][0], pk[2 * kc + 1][1], b10, b11);
            }
        }

        CP_WAIT0();
        __syncthreads();
    }

    // ---- merge key-halves into fp16 ctx smem tile ----
    float* Od = (float*)smh;                        // [128][132] fp32 partials
    float* Ld = (float*)((char*)smh + EP_LD_B);     // [128] partial l
    __half* Cs = (__half*)((char*)smh + EP_CS_B);   // [128 n][136 c] fp16 ctx
    uint32_t cs_u = qs_u + EP_CS_B;
    int row0 = qgroup * 16 + r4;
    int row1 = row0 + 8;
    if (khalf == 1) {
#pragma unroll
        for (int nf = 0; nf < 16; ++nf) {
            float2 lo; lo.x = accO[nf][0]; lo.y = accO[nf][1];
            float2 hi; hi.x = accO[nf][2]; hi.y = accO[nf][3];
            *(float2*)(Od + row0 * 132 + nf * 8 + 2 * c4) = lo;
            *(float2*)(Od + row1 * 132 + nf * 8 + 2 * c4) = hi;
        }
        if (c4 == 0) {
            Ld[row0] = accL[0];
            Ld[row1] = accL[2];
        }
    }
    __syncthreads();
    if (khalf == 0) {
        float invlo = 1.f / (accL[0] + Ld[row0]);
        float invhi = 1.f / (accL[2] + Ld[row1]);
#pragma unroll
        for (int nf = 0; nf < 16; ++nf) {
            float2 plo = *(const float2*)(Od + row0 * 132 + nf * 8 + 2 * c4);
            float2 phi = *(const float2*)(Od + row1 * 132 + nf * 8 + 2 * c4);
            *(uint32_t*)(Cs + row0 * 136 + nf * 8 + 2 * c4) =
                pack_h2((accO[nf][0] + plo.x) * invlo,
                        (accO[nf][1] + plo.y) * invlo);
            *(uint32_t*)(Cs + row1 * 136 + nf * 8 + 2 * c4) =
                pack_h2((accO[nf][2] + phi.x) * invhi,
                        (accO[nf][3] + phi.y) * invhi);
        }
    }
    __syncthreads();

    // ---- fused output GEMM: Y[o][q0+n] = WO[o][c] . ctx[n][c] + bo[o] ----
    __half* As2 = smh;  // [256 o][72] fp16, overlays dead Od
    float accD[16][4];
#pragma unroll
    for (int i = 0; i < 16; ++i)
#pragma unroll
        for (int j = 0; j < 4; ++j) accD[i][j] = 0.f;

    uint32_t a2_base = qs_u + ((w * 16 + arow) * 72 + ak8) * 2;
    uint32_t c_base = cs_u + (brow * 136 + bk8) * 2;

    for (int c0 = 0; c0 < CK; c0 += 64) {
        if (c0) __syncthreads();
#pragma unroll
        for (int i = 0; i < 8; ++i) {
            int idx = tid + i * 512;
            int oo = idx >> 4, cq = idx & 15;
            float4 v = *(const float4*)(WO + (size_t)oo * CK + c0 + cq * 4);
            uint2 u;
            u.x = pack_h2(v.x, v.y);
            u.y = pack_h2(v.z, v.w);
            *(uint2*)(As2 + oo * 72 + cq * 4) = u;
        }
        __syncthreads();

#pragma unroll
        for (int kc = 0; kc < 4; ++kc) {
            uint32_t a0, a1, a2, a3;
            ldsm_x4(a0, a1, a2, a3, a2_base + kc * 32);
#pragma unroll
            for (int nfp = 0; nfp < 8; ++nfp) {
                uint32_t b00, b01, b10, b11;
                ldsm_x4(b00, b01, b10, b11,
                        c_base + (nfp * 16 * 136 + c0) * 2 + kc * 32);
                mma_f16(accD[2 * nfp], a0, a1, a2, a3, b00, b01);
                mma_f16(accD[2 * nfp + 1], a0, a1, a2, a3, b10, b11);
            }
        }
    }

    float* Yb = Y + (size_t)b * (size_t)COUT * N_;
    int olo = w * 16 + r4;
    float blo = __ldg(bo + olo), bhi = __ldg(bo + olo + 8);
#pragma unroll
    for (int nf = 0; nf < 16; ++nf) {
        int n = q0 + nf * 8 + 2 * c4;
        float2 lo, hi;
        lo.x = accD[nf][0] + blo; lo.y = accD[nf][1] + blo;
        hi.x = accD[nf][2] + bhi; hi.y = accD[nf][3] + bhi;
        *(float2*)(Yb + (size_t)olo * N_ + n) = lo;
        *(float2*)(Yb + (size_t)(olo + 8) * N_ + n) = hi;
    }
}

// ---------------- launch ----------------
extern "C" void kernel_launch(void* const* d_in, const int* in_sizes, int n_in,
                              void* d_out, int out_size) {
    const float* x_enc = (const float*)d_in[0];
    const float* x_dec = (const float*)d_in[1];
    const float* wk    = (const float*)d_in[2];
    const float* bk    = (const float*)d_in[3];
    const float* gk    = (const float*)d_in[4];
    const float* betak = (const float*)d_in[5];
    const float* mk    = (const float*)d_in[6];
    const float* vk    = (const float*)d_in[7];
    const float* wq    = (const float*)d_in[8];
    const float* bq    = (const float*)d_in[9];
    const float* gq    = (const float*)d_in[10];
    const float* betaq = (const float*)d_in[11];
    const float* mq    = (const float*)d_in[12];
    const float* vq    = (const float*)d_in[13];
    const float* wv    = (const float*)d_in[14];
    const float* bv    = (const float*)d_in[15];
    const float* wo    = (const float*)d_in[16];
    const float* bo    = (const float*)d_in[17];
    float* out = (float*)d_out;

    __half *pqh, *pkh, *pvth;
    cudaGetSymbolAddress((void**)&pqh, g_qh);
    cudaGetSymbolAddress((void**)&pkh, g_kh);
    cudaGetSymbolAddress((void**)&pvth, g_vth);

    cudaFuncSetAttribute(gemm_tc_proj3, cudaFuncAttributeMaxDynamicSharedMemorySize, PJ_SMEM);
    cudaFuncSetAttribute(flash_mma, cudaFuncAttributeMaxDynamicSharedMemorySize, SMEM_FLASH);

    gemm_tc_proj3<<<dim3(N_ / 128, 3, B_), 256, PJ_SMEM>>>(
        x_dec, x_enc, wq, wk, wv, bq, bk, bv,
        gq, betaq, mq, vq, gk, betak, mk, vk,
        pqh, pkh, pvth);

    flash_mma<<<dim3(N_ / 128, B_), 512, SMEM_FLASH>>>(pqh, pkh, pvth, wo, bo, out);
}

// round 17
// speedup vs baseline: 1.0144x; 1.0144x over previous
#include <cuda_runtime.h>
#include <cuda_fp16.h>
#include <cstdint>

#define B_   4
#define N_   4096
#define CIN  256
#define CK   128
#define COUT 256

// ---------------- scratch (no allocs allowed) ----------------
__device__ __half g_qh[B_ * N_ * CK];   // [b][n][128] fp16, pre-scaled by log2e/sqrt(128)
__device__ __half g_kh[B_ * N_ * CK];   // [b][n][128] fp16
__device__ __half g_vth[B_ * CK * N_];  // [b][d][n] fp16 (transposed V)

// ================= helpers =================
__device__ __forceinline__ uint32_t pack_h2(float lo, float hi) {
    __half2 h = __floats2half2_rn(lo, hi);
    return *(uint32_t*)&h;
}
__device__ __forceinline__ uint32_t h2exp2_(uint32_t x) {
    uint32_t r;
    asm("ex2.approx.f16x2 %0, %1;" : "=r"(r) : "r"(x));
    return r;
}
__device__ __forceinline__ void mma_f16(float* d, uint32_t a0, uint32_t a1,
                                        uint32_t a2, uint32_t a3,
                                        uint32_t b0, uint32_t b1) {
    asm volatile(
        "mma.sync.aligned.m16n8k16.row.col.f32.f16.f16.f32 "
        "{%0,%1,%2,%3}, {%4,%5,%6,%7}, {%8,%9}, {%0,%1,%2,%3};"
        : "+f"(d[0]), "+f"(d[1]), "+f"(d[2]), "+f"(d[3])
        : "r"(a0), "r"(a1), "r"(a2), "r"(a3), "r"(b0), "r"(b1));
}
__device__ __forceinline__ void ldsm_x4(uint32_t& r0, uint32_t& r1, uint32_t& r2,
                                        uint32_t& r3, uint32_t addr) {
    asm volatile("ldmatrix.sync.aligned.m8n8.x4.shared.b16 {%0,%1,%2,%3}, [%4];"
                 : "=r"(r0), "=r"(r1), "=r"(r2), "=r"(r3) : "r"(addr));
}
__device__ __forceinline__ void ldsm_x4_t(uint32_t& r0, uint32_t& r1, uint32_t& r2,
                                          uint32_t& r3, uint32_t addr) {
    asm volatile("ldmatrix.sync.aligned.m8n8.x4.trans.shared.b16 {%0,%1,%2,%3}, [%4];"
                 : "=r"(r0), "=r"(r1), "=r"(r2), "=r"(r3) : "r"(addr));
}
#define CP_ASYNC16(dst, src) \
    asm volatile("cp.async.cg.shared.global [%0], [%1], 16;" :: "r"(dst), "l"(src) : "memory")
#define CP_COMMIT() asm volatile("cp.async.commit_group;" ::: "memory")
#define CP_WAIT0()  asm volatile("cp.async.wait_group 0;" ::: "memory")

// ======== fused 3-way projection GEMM (unchanged from R15) ========
#define PJ_APADH 136
#define PJ_BPADH 72
#define PJ_BOFFH (64 * PJ_APADH)
#define PJ_SCOFF (PJ_BOFFH + 128 * PJ_BPADH)
#define PJ_SMEM  (PJ_SCOFF * 2 + 256 * 4)
#define PJ_TPAD 136

__global__ __launch_bounds__(256, 2) void gemm_tc_proj3(
    const float* __restrict__ xdec, const float* __restrict__ xenc,
    const float* __restrict__ wq, const float* __restrict__ wk,
    const float* __restrict__ wv,
    const float* __restrict__ bq, const float* __restrict__ bk,
    const float* __restrict__ bv,
    const float* __restrict__ gq, const float* __restrict__ betaq,
    const float* __restrict__ mq, const float* __restrict__ vq,
    const float* __restrict__ gk, const float* __restrict__ betak,
    const float* __restrict__ mk, const float* __restrict__ vk,
    __half* __restrict__ yqh, __half* __restrict__ ykh, __half* __restrict__ yvt) {
    extern __shared__ __half psm[];
    __half* As = psm;
    __half* Bs = psm + PJ_BOFFH;
    float* scl = (float*)(psm + PJ_SCOFF);
    float* bef = scl + 128;
    uint32_t as_u = (uint32_t)__cvta_generic_to_shared(As);
    uint32_t bs_u = (uint32_t)__cvta_generic_to_shared(Bs);

    int which = blockIdx.y;
    const float* X = (which == 0) ? xdec : xenc;
    const float* W = (which == 0) ? wq : (which == 1) ? wk : wv;

    int b = blockIdx.z;
    int n0 = blockIdx.x * 128;
    const float* Xb = X + (size_t)b * CIN * N_;

    int tid = threadIdx.x;
    int w = tid >> 5, lane = tid & 31;
    int r4 = lane >> 2, c4 = lane & 3;

    if (which != 2 && tid < 128) {
        const float* g_ = (which == 0) ? gq : gk;
        const float* v_ = (which == 0) ? vq : vk;
        const float* b_ = (which == 0) ? bq : bk;
        const float* m_ = (which == 0) ? mq : mk;
        const float* be_ = (which == 0) ? betaq : betak;
        float sv = g_[tid] * rsqrtf(v_[tid] + 1e-5f);
        float qs = (which == 0) ? 0.12752551286084110f : 1.0f;
        scl[tid] = sv * qs;
        bef[tid] = ((b_[tid] - m_[tid]) * sv + be_[tid]) * qs;
    }

    int tc = (lane & 7) + ((lane >> 4) & 1) * 8;
    int tn = ((lane >> 3) & 1) * 8;
    int brow = (lane & 7) + ((lane >> 4) & 1) * 8;
    int bk8 = ((lane >> 3) & 1) * 8;

    uint32_t a_base = as_u + (tc * PJ_APADH + w * 16 + tn) * 2;
    uint32_t b_base = bs_u + (brow * PJ_BPADH + bk8) * 2;

    float accD[16][4];
#pragma unroll
    for (int i = 0; i < 16; ++i)
#pragma unroll
        for (int j = 0; j < 4; ++j) accD[i][j] = 0.f;

    float4 ra[8];
#pragma unroll
    for (int i = 0; i < 8; ++i) {
        int idx = tid + i * 256;
        int cc = idx >> 5, nq = idx & 31;
        ra[i] = *(const float4*)(Xb + (size_t)cc * N_ + n0 + nq * 4);
    }

    for (int c0 = 0; c0 < CIN; c0 += 64) {
        __syncthreads();
#pragma unroll
        for (int i = 0; i < 8; ++i) {
            int idx = tid + i * 256;
            int cc = idx >> 5, nq = idx & 31;
            uint2 u;
            u.x = pack_h2(ra[i].x, ra[i].y);
            u.y = pack_h2(ra[i].z, ra[i].w);
            *(uint2*)(As + cc * PJ_APADH + nq * 4) = u;
        }
#pragma unroll
        for (int i = 0; i < 8; ++i) {
            int idx = tid + i * 256;
            int oo = idx >> 4, cq = idx & 15;
            float4 v = *(const float4*)(W + (size_t)oo * CIN + c0 + cq * 4);
            uint2 u;
            u.x = pack_h2(v.x, v.y);
            u.y = pack_h2(v.z, v.w);
            *(uint2*)(Bs + oo * PJ_BPADH + cq * 4) = u;
        }
        __syncthreads();

        if (c0 + 64 < CIN) {
#pragma unroll
            for (int i = 0; i < 8; ++i) {
                int idx = tid + i * 256;
                int cc = idx >> 5, nq = idx & 31;
                ra[i] = *(const float4*)(Xb + (size_t)(c0 + 64 + cc) * N_ + n0 + nq * 4);
            }
        }

#pragma unroll
        for (int kc = 0; kc < 4; ++kc) {
            uint32_t a0, a1, a2, a3;
            ldsm_x4_t(a0, a1, a2, a3, a_base + (kc * 16 * PJ_APADH) * 2);
#pragma unroll
            for (int nfp = 0; nfp < 8; ++nfp) {
                uint32_t b00, b01, b10, b11;
                ldsm_x4(b00, b01, b10, b11,
                        b_base + (nfp * 16 * PJ_BPADH + kc * 16) * 2);
                mma_f16(accD[2 * nfp], a0, a1, a2, a3, b00, b01);
                mma_f16(accD[2 * nfp + 1], a0, a1, a2, a3, b10, b11);
            }
        }
    }

    int nl = w * 16 + r4;
    int nlo = n0 + nl;
    if (which == 2) {
        __half* Yt = yvt + (size_t)b * CK * N_;
#pragma unroll
        for (int p = 0; p < 2; ++p) {
            __syncthreads();
#pragma unroll
            for (int nf = 0; nf < 8; ++nf) {
                int nfg = p * 8 + nf;
                int o = nfg * 8 + 2 * c4;
                int ol = o - p * 64;
                float b0 = __ldg(bv + o), b1 = __ldg(bv + o + 1);
                psm[ol * PJ_TPAD + nl] = __float2half(accD[nfg][0] + b0);
                psm[(ol + 1) * PJ_TPAD + nl] = __float2half(accD[nfg][1] + b1);
                psm[ol * PJ_TPAD + nl + 8] = __float2half(accD[nfg][2] + b0);
                psm[(ol + 1) * PJ_TPAD + nl + 8] = __float2half(accD[nfg][3] + b1);
            }
            __syncthreads();
            for (int idx = tid; idx < 64 * 16; idx += 256) {
                int r = idx >> 4, ck = idx & 15;
                *(uint4*)(Yt + (size_t)(p * 64 + r) * N_ + n0 + ck * 8) =
                    *(const uint4*)(psm + r * PJ_TPAD + ck * 8);
            }
        }
    } else {
        __half* Yh = ((which == 0) ? yqh : ykh) + (size_t)b * (size_t)N_ * CK;
#pragma unroll
        for (int nf = 0; nf < 16; ++nf) {
            int o = nf * 8 + 2 * c4;
            float s0 = scl[o], s1 = scl[o + 1];
            float b0 = bef[o], b1 = bef[o + 1];
            float v0 = fmaxf(accD[nf][0] * s0 + b0, 0.f);
            float v1 = fmaxf(accD[nf][1] * s1 + b1, 0.f);
            float v2 = fmaxf(accD[nf][2] * s0 + b0, 0.f);
            float v3 = fmaxf(accD[nf][3] * s1 + b1, 0.f);
            *(uint32_t*)(Yh + (size_t)nlo * CK + o) = pack_h2(v0, v1);
            *(uint32_t*)(Yh + (size_t)(nlo + 8) * CK + o) = pack_h2(v2, v3);
        }
    }
}

// ---------------- flash attention + fused output GEMM (R15 shape, 2-tile buffers) --------
// 256 threads, warp w: qgroup=w&3 (32 rows), khalf=w>>2 (32 keys of each 64-key tile).
// K/V double-buffered in 128-key blocks: one barrier per 2 tiles.
#define QPADH 136
#define KVPAD 136
#define KBUF2 (128 * KVPAD)           // 128 K-rows (2 tiles)
#define VBUF2 (128 * KVPAD)           // 128 d-rows x 128 keys
#define OFFK_H (128 * QPADH)
#define OFFV_H (OFFK_H + 2 * KBUF2)
#define SMEM_FLASH ((OFFV_H + 2 * VBUF2) * 2)   // 174080 B
#define EXPSHIFT 5.770780163555854f
// epilogue overlay (bytes): Od [0,67584) + Ld [67584,68096) over dead Q/K0;
// Cs at OFFV_H*2 (dead V region); As2 [0,69632) after merge barrier.
#define EP_LD_B 67584
#define EP_CS_B (OFFV_H * 2)

__global__ __launch_bounds__(256, 1) void flash_mma(
    const __half* __restrict__ Qh, const __half* __restrict__ Kh,
    const __half* __restrict__ Vth, const float* __restrict__ WO,
    const float* __restrict__ bo, float* __restrict__ Y) {
    extern __shared__ __half smh[];
    __half* Qs = smh;

    int tid = threadIdx.x;
    int w = tid >> 5, lane = tid & 31;
    int qgroup = w & 3, khalf = w >> 2;
    int r4 = lane >> 2, c4 = lane & 3;
    int b = blockIdx.y;
    int q0 = blockIdx.x * 128;
    const __half* Qb = Qh + ((size_t)b * N_ + q0) * CK;
    const __half* Kb = Kh + (size_t)b * N_ * CK;
    const __half* Vtb = Vth + (size_t)b * CK * N_;

    uint32_t qs_u = (uint32_t)__cvta_generic_to_shared(smh);
    uint32_t ks_u = qs_u + OFFK_H * 2;
    uint32_t vts_u = qs_u + OFFV_H * 2;

    int arow = (lane & 7) + ((lane >> 3) & 1) * 8;
    int ak8 = (lane >> 4) * 8;
    int brow = (lane & 7) + ((lane >> 4) & 1) * 8;
    int bk8 = ((lane >> 3) & 1) * 8;

    // prologue: Q (sync) + K/V block 0 (cp.async)
    for (int idx = tid; idx < 128 * 16; idx += 256) {
        int r = idx >> 4, ck = idx & 15;
        *(uint4*)(Qs + r * QPADH + ck * 8) = *(const uint4*)(Qb + (size_t)r * CK + ck * 8);
    }
#pragma unroll
    for (int i = 0; i < 8; ++i) {
        int idx = tid + i * 256;
        int r = idx >> 4, ck = idx & 15;
        CP_ASYNC16(ks_u + (r * KVPAD + ck * 8) * 2, Kb + (size_t)r * CK + ck * 8);
    }
#pragma unroll
    for (int i = 0; i < 8; ++i) {
        int idx = tid + i * 256;
        int d = idx >> 4, ck = idx & 15;
        CP_ASYNC16(vts_u + (d * KVPAD + ck * 8) * 2, Vtb + (size_t)d * N_ + ck * 8);
    }
    CP_COMMIT();
    CP_WAIT0();
    __syncthreads();

    float accO[2][16][4];
#pragma unroll
    for (int rb = 0; rb < 2; ++rb)
#pragma unroll
        for (int i = 0; i < 16; ++i)
#pragma unroll
            for (int j = 0; j < 4; ++j) accO[rb][i][j] = 0.f;
    float accL[2][4];
#pragma unroll
    for (int rb = 0; rb < 2; ++rb)
#pragma unroll
        for (int j = 0; j < 4; ++j) accL[rb][j] = 0.f;
    const uint32_t ONES = 0x3C003C00u;

    const int kcol = khalf * 32;
    const int NB = N_ / 128;  // 32 two-tile blocks

    uint32_t qa_base0 = qs_u + (((qgroup * 32 + arow) * QPADH) + ak8) * 2;
    uint32_t qa_base1 = qa_base0 + (16 * QPADH) * 2;
    uint32_t kb_off = ((kcol + brow) * KVPAD + bk8) * 2;
    uint32_t vb_off = ((brow) * KVPAD + kcol + bk8) * 2;

    for (int tt = 0; tt < NB; ++tt) {
        uint32_t kcur_u = ks_u + (tt & 1) * (KBUF2 * 2);
        uint32_t vcur_u = vts_u + (tt & 1) * (VBUF2 * 2);

        if (tt + 1 < NB) {
            uint32_t knxt_u = ks_u + ((tt + 1) & 1) * (KBUF2 * 2);
            uint32_t vnxt_u = vts_u + ((tt + 1) & 1) * (VBUF2 * 2);
            const __half* Kg = Kb + (size_t)((tt + 1) * 128) * CK;
            int k0 = (tt + 1) * 128;
#pragma unroll
            for (int i = 0; i < 8; ++i) {
                int idx = tid + i * 256;
                int r = idx >> 4, ck = idx & 15;
                CP_ASYNC16(knxt_u + (r * KVPAD + ck * 8) * 2, Kg + (size_t)r * CK + ck * 8);
            }
#pragma unroll
            for (int i = 0; i < 8; ++i) {
                int idx = tid + i * 256;
                int d = idx >> 4, ck = idx & 15;
                CP_ASYNC16(vnxt_u + (d * KVPAD + ck * 8) * 2,
                           Vtb + (size_t)d * N_ + k0 + ck * 8);
            }
        }
        CP_COMMIT();

#pragma unroll
        for (int sub = 0; sub < 2; ++sub) {
            uint32_t ksub = kcur_u + kb_off + (sub * 64 * KVPAD) * 2;
            uint32_t vsub = vcur_u + vb_off + (sub * 64) * 2;

            // S = Q.K^T over this warp's 32 keys of this sub-tile
            float accS[2][4][4];
#pragma unroll
            for (int rb = 0; rb < 2; ++rb)
#pragma unroll
                for (int i = 0; i < 4; ++i)
#pragma unroll
                    for (int j = 0; j < 4; ++j) accS[rb][i][j] = -EXPSHIFT;
#pragma unroll
            for (int kc = 0; kc < 8; ++kc) {
                uint32_t a0[2], a1[2], a2[2], a3[2];
                ldsm_x4(a0[0], a1[0], a2[0], a3[0], qa_base0 + kc * 32);
                ldsm_x4(a0[1], a1[1], a2[1], a3[1], qa_base1 + kc * 32);
                uint32_t b00, b01, b10, b11;
                ldsm_x4(b00, b01, b10, b11, ksub + kc * 32);
                mma_f16(accS[0][0], a0[0], a1[0], a2[0], a3[0], b00, b01);
                mma_f16(accS[1][0], a0[1], a1[1], a2[1], a3[1], b00, b01);
                mma_f16(accS[0][1], a0[0], a1[0], a2[0], a3[0], b10, b11);
                mma_f16(accS[1][1], a0[1], a1[1], a2[1], a3[1], b10, b11);
                ldsm_x4(b00, b01, b10, b11, ksub + (16 * KVPAD) * 2 + kc * 32);
                mma_f16(accS[0][2], a0[0], a1[0], a2[0], a3[0], b00, b01);
                mma_f16(accS[1][2], a0[1], a1[1], a2[1], a3[1], b00, b01);
                mma_f16(accS[0][3], a0[0], a1[0], a2[0], a3[0], b10, b11);
                mma_f16(accS[1][3], a0[1], a1[1], a2[1], a3[1], b10, b11);
            }

            // P = exp2(S)
            uint32_t pk[2][4][2];
#pragma unroll
            for (int rb = 0; rb < 2; ++rb) {
#pragma unroll
                for (int nf = 0; nf < 4; ++nf) {
                    pk[rb][nf][0] = h2exp2_(pack_h2(accS[rb][nf][0], accS[rb][nf][1]));
                    pk[rb][nf][1] = h2exp2_(pack_h2(accS[rb][nf][2], accS[rb][nf][3]));
                }
            }

            // O += P.V ; l via ones-mma
#pragma unroll
            for (int kc = 0; kc < 2; ++kc) {
                mma_f16(accL[0], pk[0][2 * kc][0], pk[0][2 * kc][1],
                        pk[0][2 * kc + 1][0], pk[0][2 * kc + 1][1], ONES, ONES);
                mma_f16(accL[1], pk[1][2 * kc][0], pk[1][2 * kc][1],
                        pk[1][2 * kc + 1][0], pk[1][2 * kc + 1][1], ONES, ONES);
#pragma unroll
                for (int nf = 0; nf < 16; nf += 2) {
                    uint32_t b00, b01, b10, b11;
                    ldsm_x4(b00, b01, b10, b11,
                            vsub + (nf * 8 * KVPAD) * 2 + kc * 32);
                    mma_f16(accO[0][nf], pk[0][2 * kc][0], pk[0][2 * kc][1],
                            pk[0][2 * kc + 1][0], pk[0][2 * kc + 1][1], b00, b01);
                    mma_f16(accO[1][nf], pk[1][2 * kc][0], pk[1][2 * kc][1],
                            pk[1][2 * kc + 1][0], pk[1][2 * kc + 1][1], b00, b01);
                    mma_f16(accO[0][nf + 1], pk[0][2 * kc][0], pk[0][2 * kc][1],
                            pk[0][2 * kc + 1][0], pk[0][2 * kc + 1][1], b10, b11);
                    mma_f16(accO[1][nf + 1], pk[1][2 * kc][0], pk[1][2 * kc][1],
                            pk[1][2 * kc + 1][0], pk[1][2 * kc + 1][1], b10, b11);
                }
            }
        }

        CP_WAIT0();
        __syncthreads();  // one barrier per 2 key-tiles
    }

    // ---- merge key-halves into fp16 ctx smem tile ----
    float* Od = (float*)smh;                        // [128][132] fp32 partials
    float* Ld = (float*)((char*)smh + EP_LD_B);     // [128] partial l
    __half* Cs = (__half*)((char*)smh + EP_CS_B);   // [128 n][136 c] fp16 ctx (dead V region)
    uint32_t cs_u = qs_u + EP_CS_B;
    if (khalf == 1) {
#pragma unroll
        for (int rb = 0; rb < 2; ++rb) {
            int row0 = qgroup * 32 + rb * 16 + r4;
            int row1 = row0 + 8;
#pragma unroll
            for (int nf = 0; nf < 16; ++nf) {
                float2 lo; lo.x = accO[rb][nf][0]; lo.y = accO[rb][nf][1];
                float2 hi; hi.x = accO[rb][nf][2]; hi.y = accO[rb][nf][3];
                *(float2*)(Od + row0 * 132 + nf * 8 + 2 * c4) = lo;
                *(float2*)(Od + row1 * 132 + nf * 8 + 2 * c4) = hi;
            }
            if (c4 == 0) {
                Ld[row0] = accL[rb][0];
                Ld[row1] = accL[rb][2];
            }
        }
    }
    __syncthreads();
    if (khalf == 0) {
#pragma unroll
        for (int rb = 0; rb < 2; ++rb) {
            int row0 = qgroup * 32 + rb * 16 + r4;
            int row1 = row0 + 8;
            float invlo = 1.f / (accL[rb][0] + Ld[row0]);
            float invhi = 1.f / (accL[rb][2] + Ld[row1]);
#pragma unroll
            for (int nf = 0; nf < 16; ++nf) {
                float2 plo = *(const float2*)(Od + row0 * 132 + nf * 8 + 2 * c4);
                float2 phi = *(const float2*)(Od + row1 * 132 + nf * 8 + 2 * c4);
                *(uint32_t*)(Cs + row0 * 136 + nf * 8 + 2 * c4) =
                    pack_h2((accO[rb][nf][0] + plo.x) * invlo,
                            (accO[rb][nf][1] + plo.y) * invlo);
                *(uint32_t*)(Cs + row1 * 136 + nf * 8 + 2 * c4) =
                    pack_h2((accO[rb][nf][2] + phi.x) * invhi,
                            (accO[rb][nf][3] + phi.y) * invhi);
            }
        }
    }
    __syncthreads();

    // ---- fused output GEMM: Y[o][q0+n] = WO[o][c] . ctx[n][c] + bo[o] ----
    // WO staged in ONE shot: [256 o][136 c] fp16 over dead Od region.
    __half* As2 = smh;
#pragma unroll
    for (int i = 0; i < 32; ++i) {
        int idx = tid + i * 256;
        int oo = idx >> 5, cq = idx & 31;
        float4 v = *(const float4*)(WO + (size_t)oo * CK + cq * 4);
        uint2 u;
        u.x = pack_h2(v.x, v.y);
        u.y = pack_h2(v.z, v.w);
        *(uint2*)(As2 + oo * 136 + cq * 4) = u;
    }
    __syncthreads();

    float accD[2][16][4];
#pragma unroll
    for (int rb = 0; rb < 2; ++rb)
#pragma unroll
        for (int i = 0; i < 16; ++i)
#pragma unroll
            for (int j = 0; j < 4; ++j) accD[rb][i][j] = 0.f;

    uint32_t a2_base = qs_u + ((w * 32 + arow) * 136 + ak8) * 2;
    uint32_t c_base = cs_u + (brow * 136 + bk8) * 2;

#pragma unroll
    for (int kc = 0; kc < 8; ++kc) {
        uint32_t a0[2], a1[2], a2[2], a3[2];
        ldsm_x4(a0[0], a1[0], a2[0], a3[0], a2_base + kc * 32);
        ldsm_x4(a0[1], a1[1], a2[1], a3[1], a2_base + (16 * 136) * 2 + kc * 32);
#pragma unroll
        for (int nfp = 0; nfp < 8; ++nfp) {
            uint32_t b00, b01, b10, b11;
            ldsm_x4(b00, b01, b10, b11,
                    c_base + (nfp * 16 * 136) * 2 + kc * 32);
            mma_f16(accD[0][2 * nfp], a0[0], a1[0], a2[0], a3[0], b00, b01);
            mma_f16(accD[0][2 * nfp + 1], a0[0], a1[0], a2[0], a3[0], b10, b11);
            mma_f16(accD[1][2 * nfp], a0[1], a1[1], a2[1], a3[1], b00, b01);
            mma_f16(accD[1][2 * nfp + 1], a0[1], a1[1], a2[1], a3[1], b10, b11);
        }
    }

    float* Yb = Y + (size_t)b * (size_t)COUT * N_;
#pragma unroll
    for (int rb = 0; rb < 2; ++rb) {
        int olo = w * 32 + rb * 16 + r4;
        float blo = __ldg(bo + olo), bhi = __ldg(bo + olo + 8);
#pragma unroll
        for (int nf = 0; nf < 16; ++nf) {
            int n = q0 + nf * 8 + 2 * c4;
            float2 lo, hi;
            lo.x = accD[rb][nf][0] + blo; lo.y = accD[rb][nf][1] + blo;
            hi.x = accD[rb][nf][2] + bhi; hi.y = accD[rb][nf][3] + bhi;
            *(float2*)(Yb + (size_t)olo * N_ + n) = lo;
            *(float2*)(Yb + (size_t)(olo + 8) * N_ + n) = hi;
        }
    }
}

// ---------------- launch ----------------
extern "C" void kernel_launch(void* const* d_in, const int* in_sizes, int n_in,
                              void* d_out, int out_size) {
    const float* x_enc = (const float*)d_in[0];
    const float* x_dec = (const float*)d_in[1];
    const float* wk    = (const float*)d_in[2];
    const float* bk    = (const float*)d_in[3];
    const float* gk    = (const float*)d_in[4];
    const float* betak = (const float*)d_in[5];
    const float* mk    = (const float*)d_in[6];
    const float* vk    = (const float*)d_in[7];
    const float* wq    = (const float*)d_in[8];
    const float* bq    = (const float*)d_in[9];
    const float* gq    = (const float*)d_in[10];
    const float* betaq = (const float*)d_in[11];
    const float* mq    = (const float*)d_in[12];
    const float* vq    = (const float*)d_in[13];
    const float* wv    = (const float*)d_in[14];
    const float* bv    = (const float*)d_in[15];
    const float* wo    = (const float*)d_in[16];
    const float* bo    = (const float*)d_in[17];
    float* out = (float*)d_out;

    __half *pqh, *pkh, *pvth;
    cudaGetSymbolAddress((void**)&pqh, g_qh);
    cudaGetSymbolAddress((void**)&pkh, g_kh);
    cudaGetSymbolAddress((void**)&pvth, g_vth);

    cudaFuncSetAttribute(gemm_tc_proj3, cudaFuncAttributeMaxDynamicSharedMemorySize, PJ_SMEM);
    cudaFuncSetAttribute(flash_mma, cudaFuncAttributeMaxDynamicSharedMemorySize, SMEM_FLASH);

    gemm_tc_proj3<<<dim3(N_ / 128, 3, B_), 256, PJ_SMEM>>>(
        x_dec, x_enc, wq, wk, wv, bq, bk, bv,
        gq, betaq, mq, vq, gk, betak, mk, vk,
        pqh, pkh, pvth);

    flash_mma<<<dim3(N_ / 128, B_), 256, SMEM_FLASH>>>(pqh, pkh, pvth, wo, bo, out);
}